// round 1
// baseline (speedup 1.0000x reference)
#include <cuda_runtime.h>
#include <math.h>

#define BB 64
#define NN 128
#define LL 2

// scratch for intermediate coors/vel between layers (no allocs allowed)
__device__ float g_c0[BB*NN*2];
__device__ float g_v0[BB*NN*2];
__device__ float g_c1[BB*NN*2];
__device__ float g_v1[BB*NN*2];

__device__ __forceinline__ float siluf(float x) {
    // x * sigmoid(x); __expf accurate enough (~2^-21 rel), no cancellation
    float s = 1.0f / (1.0f + __expf(-x));
    return x * s;
}

__device__ __forceinline__ float seluf(float x) {
    const float scale = 1.0507009873554805f;
    const float alpha = 1.6732632423543772f;
    // expm1f for accuracy near 0 (cheap: only per-node, not per-edge)
    return x > 0.0f ? scale * x : scale * alpha * expm1f(x);
}

__global__ __launch_bounds__(128, 8)
void egnn_layer_kernel(const float* __restrict__ t,
                       const float* __restrict__ cin,
                       const float* __restrict__ vin,
                       float* __restrict__ cout,
                       float* __restrict__ vout,
                       const float* __restrict__ We1,
                       const float* __restrict__ be1,
                       const float* __restrict__ We2,
                       const float* __restrict__ be2,
                       const float* __restrict__ Wc1,
                       const float* __restrict__ bc1,
                       const float* __restrict__ Wc2,
                       const float* __restrict__ bc2,
                       const float* __restrict__ Wv,
                       const float* __restrict__ bv,
                       int l)
{
    // block = one (b, i); 128 threads = j
    __shared__ float  sU[16], sV[16], sW[16], sC[16];   // folded We1 + be1
    __shared__ float4 sWe2[64];      // 16 rows x 4 float4 (16 cols)
    __shared__ float  sbe2[16];
    __shared__ float4 sWc1[256];     // 16 rows x 16 float4 (64 cols)
    __shared__ float  sbc1[64];
    __shared__ float4 sWc2[16];      // 64 scalars
    __shared__ float  scj[NN*2];
    __shared__ float  stj[NN];
    __shared__ float  rax[4], ray[4];

    const int tid = threadIdx.x;
    const int b = blockIdx.x / NN;
    const int i = blockIdx.x % NN;

    // ---- load weights into shared ----
    const float* we1 = We1 + l * 8 * 16;
    if (tid < 16) {
        sU[tid]   = we1[0*16 + tid] + we1[1*16 + tid] + we1[2*16 + tid]; // hi rows (t_i)
        sV[tid]   = we1[3*16 + tid] + we1[4*16 + tid] + we1[5*16 + tid]; // hj rows (t_j)
        sW[tid]   = we1[6*16 + tid];                                     // dist row
        sC[tid]   = we1[7*16 + tid] + be1[l*16 + tid];                   // edges(=1) row + bias
        sbe2[tid] = be2[l*16 + tid];
    }
    {
        const float4* src = (const float4*)(We2 + l * 256);
        if (tid < 64) sWe2[tid] = src[tid];
    }
    {
        const float4* src = (const float4*)(Wc1 + l * 1024);
        sWc1[tid]       = src[tid];
        sWc1[tid + 128] = src[tid + 128];
    }
    if (tid < 64) sbc1[tid] = bc1[l*64 + tid];
    {
        const float4* src = (const float4*)(Wc2 + l * 64);
        if (tid < 16) sWc2[tid] = src[tid];
    }
    // coors + t for this batch
    scj[tid]       = cin[b*NN*2 + tid];
    scj[tid + 128] = cin[b*NN*2 + 128 + tid];
    stj[tid]       = t[b*NN + tid];
    __syncthreads();

    const float ci_x = scj[2*i];
    const float ci_y = scj[2*i + 1];
    const float ti   = stj[i];

    const int j = tid;
    const float dx = ci_x - scj[2*j];
    const float dy = ci_y - scj[2*j + 1];
    const float d  = fmaf(dx, dx, dy * dy);
    const float tj = stj[j];

    // x1 = silu(e_in @ We1 + be1) folded: t_i*u + t_j*v + d*w + c
    float x1[16];
    #pragma unroll
    for (int k = 0; k < 16; k++) {
        float z = fmaf(ti, sU[k], fmaf(tj, sV[k], fmaf(d, sW[k], sC[k])));
        x1[k] = siluf(z);
    }

    // q = silu(silu(x1 @ We2 + be2))  (m and silu(m) fused)
    float q[16];
    #pragma unroll
    for (int kk = 0; kk < 4; kk++) {
        float4 acc = make_float4(sbe2[4*kk], sbe2[4*kk+1], sbe2[4*kk+2], sbe2[4*kk+3]);
        #pragma unroll
        for (int n = 0; n < 16; n++) {
            float4 w = sWe2[n*4 + kk];
            float xn = x1[n];
            acc.x = fmaf(xn, w.x, acc.x);
            acc.y = fmaf(xn, w.y, acc.y);
            acc.z = fmaf(xn, w.z, acc.z);
            acc.w = fmaf(xn, w.w, acc.w);
        }
        q[4*kk+0] = siluf(siluf(acc.x));
        q[4*kk+1] = siluf(siluf(acc.y));
        q[4*kk+2] = siluf(siluf(acc.z));
        q[4*kk+3] = siluf(siluf(acc.w));
    }

    // h = silu(q @ Wc1 + bc1) ; w_ij = h @ Wc2 + bc2   (chunked over 64 cols)
    float wsum = bc2[l];
    #pragma unroll
    for (int kk = 0; kk < 16; kk++) {
        float4 acc = make_float4(sbc1[4*kk], sbc1[4*kk+1], sbc1[4*kk+2], sbc1[4*kk+3]);
        #pragma unroll
        for (int n = 0; n < 16; n++) {
            float4 w = sWc1[n*16 + kk];
            float qn = q[n];
            acc.x = fmaf(qn, w.x, acc.x);
            acc.y = fmaf(qn, w.y, acc.y);
            acc.z = fmaf(qn, w.z, acc.z);
            acc.w = fmaf(qn, w.w, acc.w);
        }
        float4 wc = sWc2[kk];
        wsum = fmaf(siluf(acc.x), wc.x, wsum);
        wsum = fmaf(siluf(acc.y), wc.y, wsum);
        wsum = fmaf(siluf(acc.z), wc.z, wsum);
        wsum = fmaf(siluf(acc.w), wc.w, wsum);
    }

    // agg partials: sum_j w_ij * (c_i - c_j)
    float ax = wsum * dx;
    float ay = wsum * dy;

    // block reduction (128 threads)
    #pragma unroll
    for (int off = 16; off > 0; off >>= 1) {
        ax += __shfl_down_sync(0xFFFFFFFFu, ax, off);
        ay += __shfl_down_sync(0xFFFFFFFFu, ay, off);
    }
    if ((tid & 31) == 0) { rax[tid >> 5] = ax; ray[tid >> 5] = ay; }
    __syncthreads();

    if (tid == 0) {
        float AX = rax[0] + rax[1] + rax[2] + rax[3];
        float AY = ray[0] + ray[1] + ray[2] + ray[3];
        // phi_v = t_i * sum(Wv) + bv
        float wv  = Wv[l*3 + 0] + Wv[l*3 + 1] + Wv[l*3 + 2];
        float phi = fmaf(ti, wv, bv[l]);
        float vx = vin[(b*NN + i)*2];
        float vy = vin[(b*NN + i)*2 + 1];
        float nvx = fmaf(phi, vx, AX);
        float nvy = fmaf(phi, vy, AY);
        float ncx = ci_x + nvx;
        float ncy = ci_y + nvy;
        cout[(b*NN + i)*2]     = seluf(ncx);
        cout[(b*NN + i)*2 + 1] = seluf(ncy);
        vout[(b*NN + i)*2]     = seluf(nvx);
        vout[(b*NN + i)*2 + 1] = seluf(nvy);
    }
}

__global__ void egnn_head_kernel(const float* __restrict__ cin,
                                 const float* __restrict__ vin,
                                 const float* __restrict__ Wconv1,
                                 const float* __restrict__ bconv1,
                                 const float* __restrict__ Wconv2,
                                 const float* __restrict__ bconv2,
                                 float* __restrict__ out)
{
    int idx = blockIdx.x * blockDim.x + threadIdx.x;
    if (idx >= BB*NN) return;

    float x0 = seluf(cin[idx*2]);
    float x1 = seluf(cin[idx*2 + 1]);
    float x2 = seluf(vin[idx*2]);
    float x3 = seluf(vin[idx*2 + 1]);

    float y0 = bconv2[0], y1 = bconv2[1], y2 = bconv2[2], y3 = bconv2[3];
    #pragma unroll
    for (int o = 0; o < 32; o++) {
        float h = bconv1[o];
        h = fmaf(x0, Wconv1[o*4 + 0], h);
        h = fmaf(x1, Wconv1[o*4 + 1], h);
        h = fmaf(x2, Wconv1[o*4 + 2], h);
        h = fmaf(x3, Wconv1[o*4 + 3], h);
        h = seluf(h);
        y0 = fmaf(h, Wconv2[0*32 + o], y0);
        y1 = fmaf(h, Wconv2[1*32 + o], y1);
        y2 = fmaf(h, Wconv2[2*32 + o], y2);
        y3 = fmaf(h, Wconv2[3*32 + o], y3);
    }
    // outputs: tuple(y[...,0:2], y[...,2:4]) flattened back-to-back
    out[idx*2]               = y0;
    out[idx*2 + 1]           = y1;
    out[BB*NN*2 + idx*2]     = y2;
    out[BB*NN*2 + idx*2 + 1] = y3;
}

extern "C" void kernel_launch(void* const* d_in, const int* in_sizes, int n_in,
                              void* d_out, int out_size)
{
    const float* t      = (const float*)d_in[0];
    const float* coors  = (const float*)d_in[1];
    const float* vel    = (const float*)d_in[2];
    const float* We1    = (const float*)d_in[3];
    const float* be1    = (const float*)d_in[4];
    const float* We2    = (const float*)d_in[5];
    const float* be2    = (const float*)d_in[6];
    const float* Wc1    = (const float*)d_in[7];
    const float* bc1    = (const float*)d_in[8];
    const float* Wc2    = (const float*)d_in[9];
    const float* bc2    = (const float*)d_in[10];
    const float* Wv     = (const float*)d_in[11];
    const float* bv     = (const float*)d_in[12];
    const float* Wconv1 = (const float*)d_in[13];
    const float* bconv1 = (const float*)d_in[14];
    const float* Wconv2 = (const float*)d_in[15];
    const float* bconv2 = (const float*)d_in[16];
    float* out = (float*)d_out;

    float *c0, *v0, *c1, *v1;
    cudaGetSymbolAddress((void**)&c0, g_c0);
    cudaGetSymbolAddress((void**)&v0, g_v0);
    cudaGetSymbolAddress((void**)&c1, g_c1);
    cudaGetSymbolAddress((void**)&v1, g_v1);

    dim3 grid(BB * NN);
    dim3 blk(128);
    egnn_layer_kernel<<<grid, blk>>>(t, coors, vel, c0, v0,
                                     We1, be1, We2, be2, Wc1, bc1, Wc2, bc2,
                                     Wv, bv, 0);
    egnn_layer_kernel<<<grid, blk>>>(t, c0, v0, c1, v1,
                                     We1, be1, We2, be2, Wc1, bc1, Wc2, bc2,
                                     Wv, bv, 1);
    egnn_head_kernel<<<(BB*NN + 127) / 128, 128>>>(c1, v1, Wconv1, bconv1,
                                                   Wconv2, bconv2, out);
}

// round 2
// speedup vs baseline: 1.4953x; 1.4953x over previous
#include <cuda_runtime.h>
#include <math.h>

#define BB 64
#define NN 128

// scratch for intermediate coors/vel between layers (no allocs allowed)
__device__ float g_c0[BB*NN*2];
__device__ float g_v0[BB*NN*2];
__device__ float g_c1[BB*NN*2];
__device__ float g_v1[BB*NN*2];

union F2U { float2 f; unsigned long long u; };

__device__ __forceinline__ float2 ffma2(float2 a, float2 b, float2 c) {
    F2U A, B, C, R;
    A.f = a; B.f = b; C.f = c;
    asm("fma.rn.f32x2 %0, %1, %2, %3;" : "=l"(R.u) : "l"(A.u), "l"(B.u), "l"(C.u));
    return R.f;
}
__device__ __forceinline__ float2 fmul2(float2 a, float2 b) {
    F2U A, B, R;
    A.f = a; B.f = b;
    asm("mul.rn.f32x2 %0, %1, %2;" : "=l"(R.u) : "l"(A.u), "l"(B.u));
    return R.f;
}
__device__ __forceinline__ float2 fadd2(float2 a, float2 b) {
    F2U A, B, R;
    A.f = a; B.f = b;
    asm("add.rn.f32x2 %0, %1, %2;" : "=l"(R.u) : "l"(A.u), "l"(B.u));
    return R.f;
}

__device__ __forceinline__ float ex2a(float x) {
    float r; asm("ex2.approx.f32 %0, %1;" : "=f"(r) : "f"(x)); return r;
}
__device__ __forceinline__ float rcpa(float x) {
    float r; asm("rcp.approx.f32 %0, %1;" : "=f"(r) : "f"(x)); return r;
}

// packed silu on an edge pair: x * sigmoid(x)
__device__ __forceinline__ float2 silu2(float2 x) {
    const float NL2E = -1.4426950408889634f;
    float2 tt = fmul2(x, make_float2(NL2E, NL2E));
    float2 e  = make_float2(ex2a(tt.x), ex2a(tt.y));
    float2 dn = fadd2(e, make_float2(1.0f, 1.0f));
    float2 r  = make_float2(rcpa(dn.x), rcpa(dn.y));
    return fmul2(x, r);
}

__device__ __forceinline__ float seluf(float x) {
    const float scale = 1.0507009873554805f;
    const float alpha = 1.6732632423543772f;
    return x > 0.0f ? scale * x : scale * alpha * expm1f(x);
}

__global__ __launch_bounds__(128, 4)
void egnn_layer_kernel(const float* __restrict__ t,
                       const float* __restrict__ cin,
                       const float* __restrict__ vin,
                       float* __restrict__ cout,
                       float* __restrict__ vout,
                       const float* __restrict__ We1,
                       const float* __restrict__ be1,
                       const float* __restrict__ We2,
                       const float* __restrict__ be2,
                       const float* __restrict__ Wc1,
                       const float* __restrict__ bc1,
                       const float* __restrict__ Wc2,
                       const float* __restrict__ bc2,
                       const float* __restrict__ Wv,
                       const float* __restrict__ bv,
                       int l)
{
    // block = (batch b, i-pair). threads 0-63: i = 2*ip, threads 64-127: i = 2*ip+1
    // each thread handles the edge pair (j=lt, j=lt+64), packed in f32x2.
    __shared__ float4 sUV[16];      // {u,u,v,v} folded We1 rows 0-2 / 3-5
    __shared__ float4 sWC[16];      // {w,w,c,c} dist row / edges row + be1
    __shared__ float2 sbe2[16];     // duplicated be2
    __shared__ float4 sWe2d[128];   // [n][c]: {w(n,2c),w(n,2c),w(n,2c+1),w(n,2c+1)}, c=0..7
    __shared__ float4 sWc1d[512];   // [n][c]: dup pairs for cols 2c,2c+1, c=0..31
    __shared__ float2 sbc1d[64];    // duplicated bc1
    __shared__ float4 sWc2d[32];    // duplicated Wc2 pairs
    __shared__ float  scj[NN*2];
    __shared__ float  stj[NN];
    __shared__ float  sredx[4], sredy[4];

    const int tid  = threadIdx.x;
    const int bb   = blockIdx.x >> 6;   // batch
    const int ip   = blockIdx.x & 63;   // i-pair
    const int half = tid >> 6;
    const int lt   = tid & 63;
    const int i    = ip * 2 + half;

    // ---- setup: fold + duplicate weights into shared ----
    const float* we1 = We1 + l * 128;
    if (tid < 16) {
        float u = we1[tid] + we1[16 + tid] + we1[32 + tid];
        float v = we1[48 + tid] + we1[64 + tid] + we1[80 + tid];
        float w = we1[96 + tid];
        float c = we1[112 + tid] + be1[l * 16 + tid];
        sUV[tid] = make_float4(u, u, v, v);
        sWC[tid] = make_float4(w, w, c, c);
        float bb2 = be2[l * 16 + tid];
        sbe2[tid] = make_float2(bb2, bb2);
    } else if (tid < 80) {
        int k = tid - 16;
        float b = bc1[l * 64 + k];
        sbc1d[k] = make_float2(b, b);
    } else if (tid < 112) {
        int k = tid - 80;
        float a = Wc2[l * 64 + 2 * k];
        float b = Wc2[l * 64 + 2 * k + 1];
        sWc2d[k] = make_float4(a, a, b, b);
    }
    {
        int n = tid >> 3, c = tid & 7;  // 128 entries, 128 threads
        float a = We2[l * 256 + n * 16 + 2 * c];
        float b = We2[l * 256 + n * 16 + 2 * c + 1];
        sWe2d[tid] = make_float4(a, a, b, b);
    }
    #pragma unroll
    for (int idx = tid; idx < 512; idx += 128) {
        int n = idx >> 5, c = idx & 31;
        float a = Wc1[l * 1024 + n * 64 + 2 * c];
        float b = Wc1[l * 1024 + n * 64 + 2 * c + 1];
        sWc1d[idx] = make_float4(a, a, b, b);
    }
    scj[tid]       = cin[bb * NN * 2 + tid];
    scj[tid + 128] = cin[bb * NN * 2 + 128 + tid];
    stj[tid]       = t[bb * NN + tid];
    __syncthreads();

    const float ci_x = scj[2 * i];
    const float ci_y = scj[2 * i + 1];
    const float ti   = stj[i];
    const float bc2l = bc2[l];

    const int j0 = lt, j1 = lt + 64;
    const float2 ti2 = make_float2(ti, ti);
    const float2 tj2 = make_float2(stj[j0], stj[j1]);
    const float2 dx2 = make_float2(ci_x - scj[2 * j0], ci_x - scj[2 * j1]);
    const float2 dy2 = make_float2(ci_y - scj[2 * j0 + 1], ci_y - scj[2 * j1 + 1]);
    const float2 d2  = ffma2(dx2, dx2, fmul2(dy2, dy2));

    // x1 = silu(folded We1 layer): z = ti*u + tj*v + d*w + c
    float2 x1[16];
    #pragma unroll
    for (int k = 0; k < 16; k++) {
        float4 uv = sUV[k];
        float4 wc = sWC[k];
        float2 z = ffma2(ti2, make_float2(uv.x, uv.y),
                  ffma2(tj2, make_float2(uv.z, uv.w),
                  ffma2(d2,  make_float2(wc.x, wc.y),
                             make_float2(wc.z, wc.w))));
        x1[k] = silu2(z);
    }

    // q = silu(silu(x1 @ We2 + be2))
    float2 q[16];
    #pragma unroll
    for (int c = 0; c < 8; c++) {
        float2 a0 = sbe2[2 * c];
        float2 a1 = sbe2[2 * c + 1];
        #pragma unroll
        for (int n = 0; n < 16; n++) {
            float4 w = sWe2d[n * 8 + c];
            a0 = ffma2(x1[n], make_float2(w.x, w.y), a0);
            a1 = ffma2(x1[n], make_float2(w.z, w.w), a1);
        }
        q[2 * c]     = silu2(silu2(a0));
        q[2 * c + 1] = silu2(silu2(a1));
    }

    // h = silu(q @ Wc1 + bc1); wsum = h @ Wc2 + bc2
    float2 wsum = make_float2(bc2l, bc2l);
    #pragma unroll 4
    for (int c = 0; c < 32; c++) {
        float2 a0 = sbc1d[2 * c];
        float2 a1 = sbc1d[2 * c + 1];
        #pragma unroll
        for (int n = 0; n < 16; n++) {
            float4 w = sWc1d[n * 32 + c];
            a0 = ffma2(q[n], make_float2(w.x, w.y), a0);
            a1 = ffma2(q[n], make_float2(w.z, w.w), a1);
        }
        float4 wc = sWc2d[c];
        wsum = ffma2(silu2(a0), make_float2(wc.x, wc.y), wsum);
        wsum = ffma2(silu2(a1), make_float2(wc.z, wc.w), wsum);
    }

    // agg partials: w_ij * (c_i - c_j), both edges
    float2 ax2 = fmul2(wsum, dx2);
    float2 ay2 = fmul2(wsum, dy2);
    float ax = ax2.x + ax2.y;
    float ay = ay2.x + ay2.y;

    // warp reduce (32 lanes), then combine 2 warps per half
    #pragma unroll
    for (int off = 16; off > 0; off >>= 1) {
        ax += __shfl_down_sync(0xFFFFFFFFu, ax, off);
        ay += __shfl_down_sync(0xFFFFFFFFu, ay, off);
    }
    const int wid = tid >> 5;
    if ((tid & 31) == 0) { sredx[wid] = ax; sredy[wid] = ay; }
    __syncthreads();

    if (lt == 0) {
        float AX = sredx[2 * half] + sredx[2 * half + 1];
        float AY = sredy[2 * half] + sredy[2 * half + 1];
        float wv  = Wv[l * 3 + 0] + Wv[l * 3 + 1] + Wv[l * 3 + 2];
        float phi = fmaf(ti, wv, bv[l]);
        float vx = vin[(bb * NN + i) * 2];
        float vy = vin[(bb * NN + i) * 2 + 1];
        float nvx = fmaf(phi, vx, AX);
        float nvy = fmaf(phi, vy, AY);
        float ncx = ci_x + nvx;
        float ncy = ci_y + nvy;
        cout[(bb * NN + i) * 2]     = seluf(ncx);
        cout[(bb * NN + i) * 2 + 1] = seluf(ncy);
        vout[(bb * NN + i) * 2]     = seluf(nvx);
        vout[(bb * NN + i) * 2 + 1] = seluf(nvy);
    }
}

__global__ void egnn_head_kernel(const float* __restrict__ cin,
                                 const float* __restrict__ vin,
                                 const float* __restrict__ Wconv1,
                                 const float* __restrict__ bconv1,
                                 const float* __restrict__ Wconv2,
                                 const float* __restrict__ bconv2,
                                 float* __restrict__ out)
{
    int idx = blockIdx.x * blockDim.x + threadIdx.x;
    if (idx >= BB * NN) return;

    float x0 = seluf(cin[idx * 2]);
    float x1 = seluf(cin[idx * 2 + 1]);
    float x2 = seluf(vin[idx * 2]);
    float x3 = seluf(vin[idx * 2 + 1]);

    float y0 = bconv2[0], y1 = bconv2[1], y2 = bconv2[2], y3 = bconv2[3];
    #pragma unroll
    for (int o = 0; o < 32; o++) {
        float h = bconv1[o];
        h = fmaf(x0, Wconv1[o * 4 + 0], h);
        h = fmaf(x1, Wconv1[o * 4 + 1], h);
        h = fmaf(x2, Wconv1[o * 4 + 2], h);
        h = fmaf(x3, Wconv1[o * 4 + 3], h);
        h = seluf(h);
        y0 = fmaf(h, Wconv2[0 * 32 + o], y0);
        y1 = fmaf(h, Wconv2[1 * 32 + o], y1);
        y2 = fmaf(h, Wconv2[2 * 32 + o], y2);
        y3 = fmaf(h, Wconv2[3 * 32 + o], y3);
    }
    out[idx * 2]                   = y0;
    out[idx * 2 + 1]               = y1;
    out[BB * NN * 2 + idx * 2]     = y2;
    out[BB * NN * 2 + idx * 2 + 1] = y3;
}

extern "C" void kernel_launch(void* const* d_in, const int* in_sizes, int n_in,
                              void* d_out, int out_size)
{
    const float* t      = (const float*)d_in[0];
    const float* coors  = (const float*)d_in[1];
    const float* vel    = (const float*)d_in[2];
    const float* We1    = (const float*)d_in[3];
    const float* be1    = (const float*)d_in[4];
    const float* We2    = (const float*)d_in[5];
    const float* be2    = (const float*)d_in[6];
    const float* Wc1    = (const float*)d_in[7];
    const float* bc1    = (const float*)d_in[8];
    const float* Wc2    = (const float*)d_in[9];
    const float* bc2    = (const float*)d_in[10];
    const float* Wv     = (const float*)d_in[11];
    const float* bv     = (const float*)d_in[12];
    const float* Wconv1 = (const float*)d_in[13];
    const float* bconv1 = (const float*)d_in[14];
    const float* Wconv2 = (const float*)d_in[15];
    const float* bconv2 = (const float*)d_in[16];
    float* out = (float*)d_out;

    float *c0, *v0, *c1, *v1;
    cudaGetSymbolAddress((void**)&c0, g_c0);
    cudaGetSymbolAddress((void**)&v0, g_v0);
    cudaGetSymbolAddress((void**)&c1, g_c1);
    cudaGetSymbolAddress((void**)&v1, g_v1);

    dim3 grid(BB * NN / 2);
    dim3 blk(128);
    egnn_layer_kernel<<<grid, blk>>>(t, coors, vel, c0, v0,
                                     We1, be1, We2, be2, Wc1, bc1, Wc2, bc2,
                                     Wv, bv, 0);
    egnn_layer_kernel<<<grid, blk>>>(t, c0, v0, c1, v1,
                                     We1, be1, We2, be2, Wc1, bc1, Wc2, bc2,
                                     Wv, bv, 1);
    egnn_head_kernel<<<(BB * NN + 127) / 128, 128>>>(c1, v1, Wconv1, bconv1,
                                                     Wconv2, bconv2, out);
}

// round 4
// speedup vs baseline: 2.2279x; 1.4899x over previous
#include <cuda_runtime.h>
#include <math.h>

#define BB 64
#define NN 128

// scratch for intermediate coors/vel between layers (no allocs allowed)
__device__ float g_c0[BB*NN*2];
__device__ float g_v0[BB*NN*2];
__device__ float g_c1[BB*NN*2];
__device__ float g_v1[BB*NN*2];

union F2U { float2 f; unsigned long long u; };

__device__ __forceinline__ float2 ffma2(float2 a, float2 b, float2 c) {
    F2U A, B, C, R;
    A.f = a; B.f = b; C.f = c;
    asm("fma.rn.f32x2 %0, %1, %2, %3;" : "=l"(R.u) : "l"(A.u), "l"(B.u), "l"(C.u));
    return R.f;
}
__device__ __forceinline__ float2 fmul2(float2 a, float2 b) {
    F2U A, B, R;
    A.f = a; B.f = b;
    asm("mul.rn.f32x2 %0, %1, %2;" : "=l"(R.u) : "l"(A.u), "l"(B.u));
    return R.f;
}

__device__ __forceinline__ float tanhaf(float x) {
    float r; asm("tanh.approx.f32 %0, %1;" : "=f"(r) : "f"(x)); return r;
}

// silu via tanh: x*sigmoid(x) = x/2 + (x/2)*tanh(x/2)  -- 1 MUFU per scalar
__device__ __forceinline__ float2 silu2(float2 x) {
    float2 h = fmul2(x, make_float2(0.5f, 0.5f));
    float t0 = tanhaf(h.x);
    float t1 = tanhaf(h.y);
    return ffma2(h, make_float2(t0, t1), h);
}

__device__ __forceinline__ float seluf(float x) {
    const float scale = 1.0507009873554805f;
    const float alpha = 1.6732632423543772f;
    return x > 0.0f ? scale * x : scale * alpha * expm1f(x);
}

__global__ __launch_bounds__(128, 4)
void egnn_layer_kernel(const float* __restrict__ t,
                       const float* __restrict__ cin,
                       const float* __restrict__ vin,
                       float* __restrict__ cout,
                       float* __restrict__ vout,
                       const float* __restrict__ We1,
                       const float* __restrict__ be1,
                       const float* __restrict__ We2,
                       const float* __restrict__ be2,
                       const float* __restrict__ Wc1,
                       const float* __restrict__ bc1,
                       const float* __restrict__ Wc2,
                       const float* __restrict__ bc2,
                       const float* __restrict__ Wv,
                       const float* __restrict__ bv,
                       int l)
{
    // block = (batch b, group of 4 i's). threads 0-63 handle i0,i1; 64-127 handle i2,i3.
    // each thread processes the j-pair (lt, lt+64) packed in f32x2 for TWO i-contexts.
    __shared__ float4 sUV[16];      // {u,u,v,v} folded We1 rows
    __shared__ float4 sWC[16];      // {w,w,c,c} dist row / const row + be1
    __shared__ float2 sbe2[16];     // duplicated be2
    __shared__ float4 sWe2d[128];   // We2 dup pairs: [n][c] {w(n,2c)x2, w(n,2c+1)x2}
    __shared__ float4 sWc1d[512];   // Wc1 dup pairs: [n][c] c=0..31
    __shared__ float2 sbc1d[64];    // duplicated bc1
    __shared__ float4 sWc2d[32];    // duplicated Wc2 pairs
    __shared__ float  scj[NN*2];
    __shared__ float  stj[NN];
    __shared__ float4 sred[4];      // per-warp {ax_a, ay_a, ax_b, ay_b}

    const int tid  = threadIdx.x;
    const int bb   = blockIdx.x >> 5;          // batch
    const int ibase = (blockIdx.x & 31) * 4;   // first of 4 i's
    const int half = tid >> 6;
    const int lt   = tid & 63;
    const int ia   = ibase + half * 2;
    const int ib   = ia + 1;

    // ---- setup: fold + duplicate weights into shared ----
    const float* we1 = We1 + l * 128;
    if (tid < 16) {
        float u = we1[tid] + we1[16 + tid] + we1[32 + tid];
        float v = we1[48 + tid] + we1[64 + tid] + we1[80 + tid];
        float w = we1[96 + tid];
        float c = we1[112 + tid] + be1[l * 16 + tid];
        sUV[tid] = make_float4(u, u, v, v);
        sWC[tid] = make_float4(w, w, c, c);
        float b2 = be2[l * 16 + tid];
        sbe2[tid] = make_float2(b2, b2);
    } else if (tid < 80) {
        int k = tid - 16;
        float b = bc1[l * 64 + k];
        sbc1d[k] = make_float2(b, b);
    } else if (tid < 112) {
        int k = tid - 80;
        float a = Wc2[l * 64 + 2 * k];
        float b = Wc2[l * 64 + 2 * k + 1];
        sWc2d[k] = make_float4(a, a, b, b);
    }
    {
        int n = tid >> 3, c = tid & 7;
        float a = We2[l * 256 + n * 16 + 2 * c];
        float b = We2[l * 256 + n * 16 + 2 * c + 1];
        sWe2d[tid] = make_float4(a, a, b, b);
    }
    #pragma unroll
    for (int idx = tid; idx < 512; idx += 128) {
        int n = idx >> 5, c = idx & 31;
        float a = Wc1[l * 1024 + n * 64 + 2 * c];
        float b = Wc1[l * 1024 + n * 64 + 2 * c + 1];
        sWc1d[idx] = make_float4(a, a, b, b);
    }
    scj[tid]       = cin[bb * NN * 2 + tid];
    scj[tid + 128] = cin[bb * NN * 2 + 128 + tid];
    stj[tid]       = t[bb * NN + tid];
    __syncthreads();

    const int j0 = lt, j1 = lt + 64;
    const float2 tj2 = make_float2(stj[j0], stj[j1]);
    const float cjx0 = scj[2 * j0],     cjy0 = scj[2 * j0 + 1];
    const float cjx1 = scj[2 * j1],     cjy1 = scj[2 * j1 + 1];

    const float ti_a = stj[ia], ti_b = stj[ib];
    const float cix_a = scj[2 * ia], ciy_a = scj[2 * ia + 1];
    const float cix_b = scj[2 * ib], ciy_b = scj[2 * ib + 1];

    const float2 dxa = make_float2(cix_a - cjx0, cix_a - cjx1);
    const float2 dya = make_float2(ciy_a - cjy0, ciy_a - cjy1);
    const float2 dxb = make_float2(cix_b - cjx0, cix_b - cjx1);
    const float2 dyb = make_float2(ciy_b - cjy0, ciy_b - cjy1);
    const float2 da  = ffma2(dxa, dxa, fmul2(dya, dya));
    const float2 db  = ffma2(dxb, dxb, fmul2(dyb, dyb));

    const float bc2l = bc2[l];

    // ---- per-context: layer1 + MLP2 -> q (sequential to bound registers) ----
    float2 q_a[16], q_b[16];
    #pragma unroll
    for (int ctx = 0; ctx < 2; ++ctx) {
        const float2 ti2 = (ctx == 0) ? make_float2(ti_a, ti_a) : make_float2(ti_b, ti_b);
        const float2 d2  = (ctx == 0) ? da : db;
        float2* q = (ctx == 0) ? q_a : q_b;

        float2 x1[16];
        #pragma unroll
        for (int k = 0; k < 16; ++k) {
            float4 uv = sUV[k];
            float4 wc = sWC[k];
            float2 z = ffma2(ti2, make_float2(uv.x, uv.y),
                      ffma2(tj2, make_float2(uv.z, uv.w),
                      ffma2(d2,  make_float2(wc.x, wc.y),
                                 make_float2(wc.z, wc.w))));
            x1[k] = silu2(z);
        }
        #pragma unroll
        for (int c = 0; c < 8; ++c) {
            float2 a0 = sbe2[2 * c];
            float2 a1 = sbe2[2 * c + 1];
            #pragma unroll
            for (int n = 0; n < 16; ++n) {
                float4 w = sWe2d[n * 8 + c];
                a0 = ffma2(x1[n], make_float2(w.x, w.y), a0);
                a1 = ffma2(x1[n], make_float2(w.z, w.w), a1);
            }
            q[2 * c]     = silu2(silu2(a0));
            q[2 * c + 1] = silu2(silu2(a1));
        }
    }

    // ---- MLP3 joint over both contexts: weight LDS amortized x2 ----
    float2 wsa = make_float2(bc2l, bc2l);
    float2 wsb = make_float2(bc2l, bc2l);
    #pragma unroll 4
    for (int c = 0; c < 32; ++c) {
        float2 bia0 = sbc1d[2 * c];
        float2 bia1 = sbc1d[2 * c + 1];
        float2 aa0 = bia0, aa1 = bia1;
        float2 ba0 = bia0, ba1 = bia1;
        #pragma unroll
        for (int n = 0; n < 16; ++n) {
            float4 w = sWc1d[n * 32 + c];
            float2 wlo = make_float2(w.x, w.y);
            float2 whi = make_float2(w.z, w.w);
            aa0 = ffma2(q_a[n], wlo, aa0);
            aa1 = ffma2(q_a[n], whi, aa1);
            ba0 = ffma2(q_b[n], wlo, ba0);
            ba1 = ffma2(q_b[n], whi, ba1);
        }
        float4 wc2 = sWc2d[c];
        float2 w0 = make_float2(wc2.x, wc2.y);
        float2 w1 = make_float2(wc2.z, wc2.w);
        wsa = ffma2(silu2(aa0), w0, wsa);
        wsa = ffma2(silu2(aa1), w1, wsa);
        wsb = ffma2(silu2(ba0), w0, wsb);
        wsb = ffma2(silu2(ba1), w1, wsb);
    }

    // agg partials: w_ij * (c_i - c_j)
    float2 axa2 = fmul2(wsa, dxa);
    float2 aya2 = fmul2(wsa, dya);
    float2 axb2 = fmul2(wsb, dxb);
    float2 ayb2 = fmul2(wsb, dyb);
    float axa = axa2.x + axa2.y;
    float aya = aya2.x + aya2.y;
    float axb = axb2.x + axb2.y;
    float ayb = ayb2.x + ayb2.y;

    #pragma unroll
    for (int off = 16; off > 0; off >>= 1) {
        axa += __shfl_down_sync(0xFFFFFFFFu, axa, off);
        aya += __shfl_down_sync(0xFFFFFFFFu, aya, off);
        axb += __shfl_down_sync(0xFFFFFFFFu, axb, off);
        ayb += __shfl_down_sync(0xFFFFFFFFu, ayb, off);
    }
    const int wid = tid >> 5;
    if ((tid & 31) == 0) sred[wid] = make_float4(axa, aya, axb, ayb);
    __syncthreads();

    if (tid < 4) {
        const int i = ibase + tid;
        const int w0 = (tid >> 1) * 2;       // warps 0,1 for i0/i1; warps 2,3 for i2/i3
        float AX, AY;
        if ((tid & 1) == 0) {
            AX = sred[w0].x + sred[w0 + 1].x;
            AY = sred[w0].y + sred[w0 + 1].y;
        } else {
            AX = sred[w0].z + sred[w0 + 1].z;
            AY = sred[w0].w + sred[w0 + 1].w;
        }
        float ti  = stj[i];
        float cix = scj[2 * i];
        float ciy = scj[2 * i + 1];
        float wv  = Wv[l * 3] + Wv[l * 3 + 1] + Wv[l * 3 + 2];
        float phi = fmaf(ti, wv, bv[l]);
        float vx = vin[(bb * NN + i) * 2];
        float vy = vin[(bb * NN + i) * 2 + 1];
        float nvx = fmaf(phi, vx, AX);
        float nvy = fmaf(phi, vy, AY);
        float ncx = cix + nvx;
        float ncy = ciy + nvy;
        cout[(bb * NN + i) * 2]     = seluf(ncx);
        cout[(bb * NN + i) * 2 + 1] = seluf(ncy);
        vout[(bb * NN + i) * 2]     = seluf(nvx);
        vout[(bb * NN + i) * 2 + 1] = seluf(nvy);
    }
}

__global__ void egnn_head_kernel(const float* __restrict__ cin,
                                 const float* __restrict__ vin,
                                 const float* __restrict__ Wconv1,
                                 const float* __restrict__ bconv1,
                                 const float* __restrict__ Wconv2,
                                 const float* __restrict__ bconv2,
                                 float* __restrict__ out)
{
    int idx = blockIdx.x * blockDim.x + threadIdx.x;
    if (idx >= BB * NN) return;

    float x0 = seluf(cin[idx * 2]);
    float x1 = seluf(cin[idx * 2 + 1]);
    float x2 = seluf(vin[idx * 2]);
    float x3 = seluf(vin[idx * 2 + 1]);

    float y0 = bconv2[0], y1 = bconv2[1], y2 = bconv2[2], y3 = bconv2[3];
    #pragma unroll
    for (int o = 0; o < 32; o++) {
        float h = bconv1[o];
        h = fmaf(x0, Wconv1[o * 4 + 0], h);
        h = fmaf(x1, Wconv1[o * 4 + 1], h);
        h = fmaf(x2, Wconv1[o * 4 + 2], h);
        h = fmaf(x3, Wconv1[o * 4 + 3], h);
        h = seluf(h);
        y0 = fmaf(h, Wconv2[0 * 32 + o], y0);
        y1 = fmaf(h, Wconv2[1 * 32 + o], y1);
        y2 = fmaf(h, Wconv2[2 * 32 + o], y2);
        y3 = fmaf(h, Wconv2[3 * 32 + o], y3);
    }
    out[idx * 2]                   = y0;
    out[idx * 2 + 1]               = y1;
    out[BB * NN * 2 + idx * 2]     = y2;
    out[BB * NN * 2 + idx * 2 + 1] = y3;
}

extern "C" void kernel_launch(void* const* d_in, const int* in_sizes, int n_in,
                              void* d_out, int out_size)
{
    const float* t      = (const float*)d_in[0];
    const float* coors  = (const float*)d_in[1];
    const float* vel    = (const float*)d_in[2];
    const float* We1    = (const float*)d_in[3];
    const float* be1    = (const float*)d_in[4];
    const float* We2    = (const float*)d_in[5];
    const float* be2    = (const float*)d_in[6];
    const float* Wc1    = (const float*)d_in[7];
    const float* bc1    = (const float*)d_in[8];
    const float* Wc2    = (const float*)d_in[9];
    const float* bc2    = (const float*)d_in[10];
    const float* Wv     = (const float*)d_in[11];
    const float* bv     = (const float*)d_in[12];
    const float* Wconv1 = (const float*)d_in[13];
    const float* bconv1 = (const float*)d_in[14];
    const float* Wconv2 = (const float*)d_in[15];
    const float* bconv2 = (const float*)d_in[16];
    float* out = (float*)d_out;

    float *c0, *v0, *c1, *v1;
    cudaGetSymbolAddress((void**)&c0, g_c0);
    cudaGetSymbolAddress((void**)&v0, g_v0);
    cudaGetSymbolAddress((void**)&c1, g_c1);
    cudaGetSymbolAddress((void**)&v1, g_v1);

    dim3 grid(BB * 32);   // 2048 blocks: (batch, group of 4 i's)
    dim3 blk(128);
    egnn_layer_kernel<<<grid, blk>>>(t, coors, vel, c0, v0,
                                     We1, be1, We2, be2, Wc1, bc1, Wc2, bc2,
                                     Wv, bv, 0);
    egnn_layer_kernel<<<grid, blk>>>(t, c0, v0, c1, v1,
                                     We1, be1, We2, be2, Wc1, bc1, Wc2, bc2,
                                     Wv, bv, 1);
    egnn_head_kernel<<<(BB * NN + 127) / 128, 128>>>(c1, v1, Wconv1, bconv1,
                                                     Wconv2, bconv2, out);
}